// round 8
// baseline (speedup 1.0000x reference)
#include <cuda_runtime.h>
#include <cstdint>

// AR(24) rollout, block-recurrence form.
// y_{t} for a block of L=8 steps is a dense [8 x 24] matvec (matrix M) against
// the window at block start, + bias coefficient B[i]*b. Inside a block the 8
// outputs are INDEPENDENT (ILP=8) -> fma pipe can saturate; the serial AR
// dependency survives only at block granularity (21 blocks of 8 = 168).
// M/B are built once by a 1-warp prep kernel (constant across all b,d) into
// __device__ scratch, staged dup-packed in SMEM, consumed via broadcast
// LDS.128 feeding packed fma.rn.f32x2.
//
// Shapes: x [256,336,512] f32, W [24,1] f32, b [1] f32, out [256,168,512] f32

#define ORDER 24
#define T_OUT 168
#define D_DIM 512
#define B_DIM 256
#define S_DIM 336
#define HALF_D (D_DIM / 2)
#define BLOCK 128
#define L 8                      // outputs per block-step; 24/8=3 phases

__device__ unsigned long long d_M2[L * ORDER];  // dup-packed M[i][k]
__device__ unsigned long long d_B2[L];          // dup-packed B[i]*bias

// ---- prep: build M and B (single warp; lanes 0..23 = columns, lane 24 = bias)
__global__ void ar_prep_kernel(const float* __restrict__ W,
                               const float* __restrict__ bias) {
    const int k = threadIdx.x;
    if (k > ORDER) return;
    const bool is_bias = (k == ORDER);
    const float bval = __ldg(bias);

    float col[L];
#pragma unroll
    for (int i = 0; i < L; i++) {
        float v;
        if (is_bias) v = 1.0f;                       // constant-term coefficient
        else         v = (k >= i) ? __ldg(&W[k - i]) : 0.0f;
#pragma unroll
        for (int m = 0; m < i; m++)
            v += __ldg(&W[ORDER - i + m]) * col[m];
        col[i] = v;
        unsigned int u = __float_as_uint(is_bias ? v * bval : v);
        unsigned long long packed =
            ((unsigned long long)u << 32) | (unsigned long long)u;
        if (is_bias) d_B2[i] = packed;
        else         d_M2[i * ORDER + k] = packed;
    }
}

// ---- main: 65536 threads, one thread = two adjacent d channels
__global__ __launch_bounds__(BLOCK, 4)
void ar_block_kernel(const float* __restrict__ x,
                     float* __restrict__ out) {
    __shared__ __align__(16) unsigned long long M2s[L * ORDER];
    __shared__ __align__(16) unsigned long long B2s[L];

    const int tid = threadIdx.x;
    for (int idx = tid; idx < L * ORDER + L; idx += BLOCK) {
        if (idx < L * ORDER) M2s[idx] = d_M2[idx];
        else                 B2s[idx - L * ORDER] = d_B2[idx - L * ORDER];
    }

    const int p = blockIdx.x * BLOCK + tid;   // pair index in [0, B*HALF_D)
    const int b = p / HALF_D;
    const int d = (p - b * HALF_D) * 2;

    // seed window: last ORDER timesteps (coalesced 8B loads)
    unsigned long long win[ORDER];
    const float* xp = x + (size_t)b * S_DIM * D_DIM
                        + (size_t)(S_DIM - ORDER) * D_DIM + d;
#pragma unroll
    for (int k = 0; k < ORDER; k++)
        win[k] = *reinterpret_cast<const unsigned long long*>(xp + (size_t)k * D_DIM);

    __syncthreads();

    unsigned int m2_addr, b2_addr;
    asm("{ .reg .u64 t; cvta.to.shared.u64 t, %1; cvt.u32.u64 %0, t; }"
        : "=r"(m2_addr) : "l"(M2s));
    asm("{ .reg .u64 t; cvta.to.shared.u64 t, %1; cvt.u32.u64 %0, t; }"
        : "=r"(b2_addr) : "l"(B2s));

    float* op = out + (size_t)b * T_OUT * D_DIM + d;

    // 21 blocks of 8; window phase cycles 0,8,16. Fully unrolled inner so
    // (base+k)%24 is compile-time and the window stays in fixed registers.
#pragma unroll 1
    for (int outer = 0; outer < T_OUT / ORDER; outer++) {
#pragma unroll
        for (int ph = 0; ph < 3; ph++) {
            const int base = ph * L;
            unsigned long long ynew[L];
#pragma unroll
            for (int i = 0; i < L; i++) {
                unsigned long long acc;
                asm volatile("ld.shared.b64 %0, [%1];"
                             : "=l"(acc) : "r"(b2_addr + 8u * i));
#pragma unroll
                for (int j = 0; j < ORDER / 2; j++) {
                    unsigned long long c0, c1;
                    asm volatile("ld.shared.v2.b64 {%0, %1}, [%2];"
                                 : "=l"(c0), "=l"(c1)
                                 : "r"(m2_addr + (unsigned)(i * ORDER * 8 + 16 * j)));
                    asm("fma.rn.f32x2 %0, %1, %2, %0;" : "+l"(acc)
                        : "l"(c0), "l"(win[(base + 2 * j) % ORDER]));
                    asm("fma.rn.f32x2 %0, %1, %2, %0;" : "+l"(acc)
                        : "l"(c1), "l"(win[(base + 2 * j + 1) % ORDER]));
                }
                ynew[i] = acc;
                *reinterpret_cast<unsigned long long*>(
                    op + (size_t)(outer * ORDER + base + i) * D_DIM) = acc;
            }
            // commit new values only after all 8 reads of the old window
#pragma unroll
            for (int i = 0; i < L; i++)
                win[(base + i) % ORDER] = ynew[i];
        }
    }
}

extern "C" void kernel_launch(void* const* d_in, const int* in_sizes, int n_in,
                              void* d_out, int out_size) {
    const float* x  = (const float*)d_in[0];   // [256, 336, 512]
    const float* W  = (const float*)d_in[1];   // [24, 1]
    const float* bs = (const float*)d_in[2];   // [1]
    float* out = (float*)d_out;                // [256, 168, 512]

    ar_prep_kernel<<<1, 32>>>(W, bs);
    const int n_threads = B_DIM * HALF_D;      // 65536
    ar_block_kernel<<<n_threads / BLOCK, BLOCK>>>(x, out);
}

// round 9
// speedup vs baseline: 1.4214x; 1.4214x over previous
#include <cuda_runtime.h>
#include <cstdint>

// AR(24) rollout, fully unrolled to a closed-form affine map (R9).
// y[t] = sum_k M[t][k] * win0[k] + C[t]*b  with M[168][24], C[168] constant
// across all (b,d): built once by a 1-warp prep kernel, staged dup-packed in
// SMEM, consumed via broadcast LDS feeding packed fma.rn.f32x2.
// NO recurrence in the main kernel -> unlimited ILP across t, and the 4032
// coefficients cannot be register-hoisted -> no spill cliff (killed R5/6/8).
//
// Shapes: x [256,336,512] f32, W [24,1] f32, b [1] f32, out [256,168,512] f32

#define ORDER 24
#define T_OUT 168
#define D_DIM 512
#define B_DIM 256
#define S_DIM 336
#define HALF_D (D_DIM / 2)
#define BLOCK 128

__device__ unsigned long long d_M2[T_OUT * ORDER];  // dup-packed M[t][k]
__device__ unsigned long long d_C2[T_OUT];          // dup-packed C[t]*bias

// ---- prep: one warp. lane k<24 owns column k of M; lane 24 owns C.
__global__ void ar_prep_kernel(const float* __restrict__ W,
                               const float* __restrict__ bias) {
    const int k = threadIdx.x;
    if (k > ORDER) return;
    const bool is_bias = (k == ORDER);
    const float bval = __ldg(bias);

    float w[ORDER];
    for (int j = 0; j < ORDER; j++) w[j] = __ldg(&W[j]);

    float hist[ORDER];  // this column's M[m][k] for the last 24 m
    for (int t = 0; t < T_OUT; t++) {
        float v;
        if (is_bias) v = 1.0f;
        else         v = (t <= k) ? w[k - t] : 0.0f;
        int jstart = ORDER - t; if (jstart < 0) jstart = 0;
        for (int j = jstart; j < ORDER; j++) {
            int m = t + j - ORDER;          // in [max(0,t-24), t-1]
            v += w[j] * hist[m % ORDER];
        }
        hist[t % ORDER] = v;
        float s = is_bias ? v * bval : v;
        unsigned int u = __float_as_uint(s);
        unsigned long long packed =
            ((unsigned long long)u << 32) | (unsigned long long)u;
        if (is_bias) d_C2[t] = packed;
        else         d_M2[t * ORDER + k] = packed;
    }
}

// ---- main: 65536 threads, one thread = two adjacent d channels.
__global__ __launch_bounds__(BLOCK, 4)
void ar_matvec_kernel(const float* __restrict__ x,
                      float* __restrict__ out) {
    __shared__ __align__(16) unsigned long long M2s[T_OUT * ORDER];
    __shared__ __align__(16) unsigned long long C2s[T_OUT];

    const int tid = threadIdx.x;
    for (int idx = tid; idx < T_OUT * ORDER; idx += BLOCK) M2s[idx] = d_M2[idx];
    for (int idx = tid; idx < T_OUT; idx += BLOCK)         C2s[idx] = d_C2[idx];

    const int p = blockIdx.x * BLOCK + tid;   // pair index in [0, B*HALF_D)
    const int b = p / HALF_D;
    const int d = (p - b * HALF_D) * 2;

    // seed window: last ORDER timesteps (coalesced 8B loads), read-only.
    unsigned long long win[ORDER];
    const float* xp = x + (size_t)b * S_DIM * D_DIM
                        + (size_t)(S_DIM - ORDER) * D_DIM + d;
#pragma unroll
    for (int k = 0; k < ORDER; k++)
        win[k] = *reinterpret_cast<const unsigned long long*>(xp + (size_t)k * D_DIM);

    __syncthreads();

    unsigned int m2_addr, c2_addr;
    asm("{ .reg .u64 t; cvta.to.shared.u64 t, %1; cvt.u32.u64 %0, t; }"
        : "=r"(m2_addr) : "l"(M2s));
    asm("{ .reg .u64 t; cvta.to.shared.u64 t, %1; cvt.u32.u64 %0, t; }"
        : "=r"(c2_addr) : "l"(C2s));

    float* op = out + (size_t)b * T_OUT * D_DIM + d;

    // 168 outputs, 4 independent dot-products in flight per outer iteration.
#pragma unroll 1
    for (int t0 = 0; t0 < T_OUT; t0 += 4) {
#pragma unroll
        for (int u = 0; u < 4; u++) {
            const int t = t0 + u;
            unsigned long long acc;
            asm("ld.shared.b64 %0, [%1];"
                : "=l"(acc) : "r"(c2_addr + 8u * t));
#pragma unroll
            for (int j = 0; j < ORDER / 2; j++) {
                unsigned long long c0, c1;
                asm("ld.shared.v2.b64 {%0, %1}, [%2];"
                    : "=l"(c0), "=l"(c1)
                    : "r"(m2_addr + (unsigned)(t * ORDER * 8 + 16 * j)));
                asm("fma.rn.f32x2 %0, %1, %2, %0;" : "+l"(acc)
                    : "l"(c0), "l"(win[2 * j]));
                asm("fma.rn.f32x2 %0, %1, %2, %0;" : "+l"(acc)
                    : "l"(c1), "l"(win[2 * j + 1]));
            }
            *reinterpret_cast<unsigned long long*>(
                op + (size_t)t * D_DIM) = acc;
        }
    }
}

extern "C" void kernel_launch(void* const* d_in, const int* in_sizes, int n_in,
                              void* d_out, int out_size) {
    const float* x  = (const float*)d_in[0];   // [256, 336, 512]
    const float* W  = (const float*)d_in[1];   // [24, 1]
    const float* bs = (const float*)d_in[2];   // [1]
    float* out = (float*)d_out;                // [256, 168, 512]

    ar_prep_kernel<<<1, 32>>>(W, bs);
    const int n_threads = B_DIM * HALF_D;      // 65536
    ar_matvec_kernel<<<n_threads / BLOCK, BLOCK>>>(x, out);
}

// round 10
// speedup vs baseline: 5.6609x; 3.9826x over previous
#include <cuda_runtime.h>
#include <cstdint>

// AR(24) rollout: out[b, t, d], t in [0,168), seeded from x[b, 312..335, d].
// One thread = two adjacent d channels via packed fma.rn.f32x2 (FFMA2).
// R10: R6's 2-chain accumulator split, but with the register cap RAISED.
// Occupancy is grid-limited (65536 total threads = ~443/SM resident), so up
// to 64K/448 ~= 146 regs/thread costs nothing. launch_bounds(64,7) sets the
// ptxas cap to 146 (vs the 128 cap that caused the R5/R6/R8 wk[] spills).
// Weights + window + both accumulator chains all live in registers; the
// inner loop has ZERO memory ops except the one output store.
//
// Shapes: x [256,336,512] f32, W [24,1] f32, b [1] f32, out [256,168,512] f32

#define ORDER 24
#define T_OUT 168
#define D_DIM 512
#define B_DIM 256
#define S_DIM 336
#define HALF_D (D_DIM / 2)
#define BLOCK 64

__global__ __launch_bounds__(BLOCK, 7)   // reg cap = 65536/(64*7) = 146
void ar_ffma2_kernel(const float* __restrict__ x,
                     const float* __restrict__ W,
                     const float* __restrict__ bias,
                     float* __restrict__ out) {
    const int p = blockIdx.x * BLOCK + threadIdx.x;  // pair index
    const int b = p / HALF_D;
    const int d = (p - b * HALF_D) * 2;

    // duplicated-pair coefficients (lo == hi == W[k]) in registers
    unsigned long long wk[ORDER];
#pragma unroll
    for (int k = 0; k < ORDER; k++) {
        unsigned int wi = __float_as_uint(__ldg(&W[k]));
        wk[k] = ((unsigned long long)wi << 32) | (unsigned long long)wi;
    }
    unsigned long long bias2;
    {
        unsigned int bi = __float_as_uint(__ldg(bias));
        bias2 = ((unsigned long long)bi << 32) | (unsigned long long)bi;
    }

    // seed window: last ORDER timesteps (coalesced 8B loads)
    unsigned long long win[ORDER];
    const float* xp = x + (size_t)b * S_DIM * D_DIM
                        + (size_t)(S_DIM - ORDER) * D_DIM + d;
#pragma unroll
    for (int k = 0; k < ORDER; k++)
        win[k] = *reinterpret_cast<const unsigned long long*>(xp + (size_t)k * D_DIM);

    float* op = out + (size_t)b * T_OUT * D_DIM + d;

    // 168 = 7 * 24; inner 24 steps fully unrolled -> (i+k)%24 compile-time.
#pragma unroll 1
    for (int outer = 0; outer < T_OUT / ORDER; outer++) {
#pragma unroll
        for (int i = 0; i < ORDER; i++) {
            // two independent chains: k in [0,12) and [12,24).
            // win[i] (written by the previous step) is consumed only at k=23,
            // the tail of chain 1 -> cross-step serial path stays 1 FMA.
            unsigned long long a0 = bias2, a1;
            asm("mul.rn.f32x2 %0, %1, %2;" : "=l"(a1)
                : "l"(wk[12]), "l"(win[(i + 12) % ORDER]));
#pragma unroll
            for (int k = 0; k < 12; k++) {
                asm("fma.rn.f32x2 %0, %1, %2, %0;" : "+l"(a0)
                    : "l"(wk[k]), "l"(win[(i + k) % ORDER]));
            }
#pragma unroll
            for (int k = 13; k < 24; k++) {
                asm("fma.rn.f32x2 %0, %1, %2, %0;" : "+l"(a1)
                    : "l"(wk[k]), "l"(win[(i + k) % ORDER]));
            }
            unsigned long long acc;
            asm("add.rn.f32x2 %0, %1, %2;" : "=l"(acc) : "l"(a0), "l"(a1));

            win[i] = acc;
            *reinterpret_cast<unsigned long long*>(
                op + (size_t)(outer * ORDER + i) * D_DIM) = acc;
        }
    }
}

extern "C" void kernel_launch(void* const* d_in, const int* in_sizes, int n_in,
                              void* d_out, int out_size) {
    const float* x  = (const float*)d_in[0];   // [256, 336, 512]
    const float* W  = (const float*)d_in[1];   // [24, 1]
    const float* bs = (const float*)d_in[2];   // [1]
    float* out = (float*)d_out;                // [256, 168, 512]

    const int n_threads = B_DIM * HALF_D;      // 65536
    ar_ffma2_kernel<<<n_threads / BLOCK, BLOCK>>>(x, W, bs, out);
}

// round 11
// speedup vs baseline: 6.2371x; 1.1018x over previous
#include <cuda_runtime.h>
#include <cstdint>

// AR(24) rollout: out[b, t, d], t in [0,168), seeded from x[b, 312..335, d].
// R11: one thread = FOUR contiguous d channels = two independent dup-packed
// FFMA2 column streams (A: d..d+1, B: d+2..d+3) sharing one register-resident
// wk[]. ILP=2 comes from independent data (no accumulator-splitting inside a
// chain -- that path triggered ptxas demotion in R5/6/10). Single accumulator
// per column, exactly R3's proven chain structure, duplicated.
// Loads are LDG.128, stores are STG.128. No launch_bounds: occupancy is
// grid-limited (32768 threads ~ 221/SM), default 255-reg cap leaves ptxas
// slack so its spill heuristic stays quiet.
//
// Shapes: x [256,336,512] f32, W [24,1] f32, b [1] f32, out [256,168,512] f32

#define ORDER 24
#define T_OUT 168
#define D_DIM 512
#define B_DIM 256
#define S_DIM 336
#define QUAD_D (D_DIM / 4)
#define BLOCK 64

__global__ void ar_ffma2x2_kernel(const float* __restrict__ x,
                                  const float* __restrict__ W,
                                  const float* __restrict__ bias,
                                  float* __restrict__ out) {
    const int p = blockIdx.x * BLOCK + threadIdx.x;  // quad index
    const int b = p / QUAD_D;
    const int d = (p - b * QUAD_D) * 4;

    // duplicated-pair coefficients (lo == hi == W[k]) in registers
    unsigned long long wk[ORDER];
#pragma unroll
    for (int k = 0; k < ORDER; k++) {
        unsigned int wi = __float_as_uint(__ldg(&W[k]));
        wk[k] = ((unsigned long long)wi << 32) | (unsigned long long)wi;
    }
    unsigned long long bias2;
    {
        unsigned int bi = __float_as_uint(__ldg(bias));
        bias2 = ((unsigned long long)bi << 32) | (unsigned long long)bi;
    }

    // seed both windows: last ORDER timesteps, one LDG.128 per step
    unsigned long long winA[ORDER], winB[ORDER];
    const float* xp = x + (size_t)b * S_DIM * D_DIM
                        + (size_t)(S_DIM - ORDER) * D_DIM + d;
#pragma unroll
    for (int k = 0; k < ORDER; k++) {
        unsigned long long a, bq;
        asm("ld.global.nc.v2.b64 {%0, %1}, [%2];"
            : "=l"(a), "=l"(bq)
            : "l"(xp + (size_t)k * D_DIM));
        winA[k] = a;
        winB[k] = bq;
    }

    float* op = out + (size_t)b * T_OUT * D_DIM + d;

    // 168 = 7 * 24; inner 24 steps fully unrolled -> (i+k)%24 compile-time.
#pragma unroll 1
    for (int outer = 0; outer < T_OUT / ORDER; outer++) {
#pragma unroll
        for (int i = 0; i < ORDER; i++) {
            // two INDEPENDENT single-accumulator chains (one per column);
            // every FMA has a dual from the other column -> ILP=2 without
            // any extra per-chain accumulator state.
            unsigned long long accA = bias2, accB = bias2;
#pragma unroll
            for (int k = 0; k < ORDER; k++) {
                asm("fma.rn.f32x2 %0, %1, %2, %0;" : "+l"(accA)
                    : "l"(wk[k]), "l"(winA[(i + k) % ORDER]));
                asm("fma.rn.f32x2 %0, %1, %2, %0;" : "+l"(accB)
                    : "l"(wk[k]), "l"(winB[(i + k) % ORDER]));
            }
            winA[i] = accA;
            winB[i] = accB;
            asm("st.global.v2.b64 [%0], {%1, %2};"
                :: "l"(op + (size_t)(outer * ORDER + i) * D_DIM),
                   "l"(accA), "l"(accB));
        }
    }
}

extern "C" void kernel_launch(void* const* d_in, const int* in_sizes, int n_in,
                              void* d_out, int out_size) {
    const float* x  = (const float*)d_in[0];   // [256, 336, 512]
    const float* W  = (const float*)d_in[1];   // [24, 1]
    const float* bs = (const float*)d_in[2];   // [1]
    float* out = (float*)d_out;                // [256, 168, 512]

    const int n_threads = B_DIM * QUAD_D;      // 32768
    ar_ffma2x2_kernel<<<n_threads / BLOCK, BLOCK>>>(x, W, bs, out);
}